// round 8
// baseline (speedup 1.0000x reference)
#include <cuda_runtime.h>

// QuantumLayer collapses analytically to out[b] = cos(x[b,0] + weights[0]):
//  - RY(w)RY(x)|0> = RY(x+w)|0> (angles add; product state).
//  - Qubit 0 is only ever a CNOT control; Z_0 commutes with the chain.
//  - <Z_0> = cos(x[b,0] + w[0]).
//
// R6 finding: kernel is MLP-starved (1.5 TB/s at 19.5% DRAM, latency-bound).
// Need ~400+ outstanding 32B sectors/SM to saturate; previous MLP=2/thread
// gave ~100. This version: 8 rows per thread, all 8 stride-8 loads
// front-batched (MLP_p1=8) -> 2048 in-flight sectors/SM.
// 128 CTAs x 256 thr x 8 = 262144 exact, one balanced wave.
// Outputs per thread are 8 consecutive floats -> two coalesced STG.128.

__global__ __launch_bounds__(256)
void quantum_layer_kernel(const float* __restrict__ x,
                          const float* __restrict__ w,
                          float* __restrict__ out,
                          int B)
{
    const float w0 = __ldg(w);
    const int t = blockIdx.x * 256 + threadIdx.x;   // 0..32767
    const int base = t * 8;                          // first row for this thread
    if (base + 7 < B) {
        const float* p = x + (size_t)base * 8;      // rows base..base+7
        float a0, a1, a2, a3, a4, a5, a6, a7;
        // front-batched: 8 independent streaming loads, one per 32B row-sector
        asm volatile("ld.global.nc.cs.f32 %0, [%1];"       : "=f"(a0) : "l"(p + 0*8));
        asm volatile("ld.global.nc.cs.f32 %0, [%1];"       : "=f"(a1) : "l"(p + 1*8));
        asm volatile("ld.global.nc.cs.f32 %0, [%1];"       : "=f"(a2) : "l"(p + 2*8));
        asm volatile("ld.global.nc.cs.f32 %0, [%1];"       : "=f"(a3) : "l"(p + 3*8));
        asm volatile("ld.global.nc.cs.f32 %0, [%1];"       : "=f"(a4) : "l"(p + 4*8));
        asm volatile("ld.global.nc.cs.f32 %0, [%1];"       : "=f"(a5) : "l"(p + 5*8));
        asm volatile("ld.global.nc.cs.f32 %0, [%1];"       : "=f"(a6) : "l"(p + 6*8));
        asm volatile("ld.global.nc.cs.f32 %0, [%1];"       : "=f"(a7) : "l"(p + 7*8));

        float4 r0, r1;
        r0.x = __cosf(a0 + w0);
        r0.y = __cosf(a1 + w0);
        r0.z = __cosf(a2 + w0);
        r0.w = __cosf(a3 + w0);
        r1.x = __cosf(a4 + w0);
        r1.y = __cosf(a5 + w0);
        r1.z = __cosf(a6 + w0);
        r1.w = __cosf(a7 + w0);
        *reinterpret_cast<float4*>(out + base)     = r0;
        *reinterpret_cast<float4*>(out + base + 4) = r1;
    } else {
        for (int b = base; b < B; ++b)
            out[b] = __cosf(__ldg(x + (size_t)b * 8) + w0);
    }
}

extern "C" void kernel_launch(void* const* d_in, const int* in_sizes, int n_in,
                              void* d_out, int out_size)
{
    const float* x = (const float*)d_in[0];   // [B, 8] float32
    const float* w = (const float*)d_in[1];   // [8]   float32
    float* out = (float*)d_out;               // [B]   float32
    int B = out_size;

    // 8 rows/thread: 262144 / 8 / 256 = 128 CTAs (exact), one wave.
    int threads = 256;
    int blocks = (B + threads * 8 - 1) / (threads * 8);
    quantum_layer_kernel<<<blocks, threads>>>(x, w, out, B);
}